// round 12
// baseline (speedup 1.0000x reference)
#include <cuda_runtime.h>
#include <float.h>
#include <math.h>

// Problem constants (shapes fixed by the dataset)
#define DIM       256
#define MAXB      128
#define TOPK      32
#define CAND_CAP  65536

#define INV_TAU   10.0f     // 1 / 0.1
#define PEN_COEF  0.25f     // BETA / (2*SIGMA^2) = 0.5 / 2
#define SIM_BOUND 10.0f     // max |q.K| / tau  (q, K unit-norm)

#define QG 32               // queries per logits tile
#define CG 64               // candidates per logits chunk
#define DH 64               // depth quarter (d-split 4)
#define NSPLIT 4
#define LX 111              // logits x-blocks
#define PRE_BLOCKS 148
#define P_PARTS 8           // selection parts per query
#define EQCAP 2048          // per-part element capacity (fast path)
#define RANKCAP 512         // rank-resolve shortcut limit
#define SVV 2048            // sampled float4s for the bound (8192 rows)

// ---------------- scratch (device globals; no allocation allowed) ----------
// Epoch-parity state: ONE ticket per BLOCK (tid==0) per kernel; epoch =
// ticket / gridSize is launch-unique and identical across all blocks of a
// launch (launches serialize on the stream). Candidate counter is double-
// buffered by epoch parity; each k_pre launch zeroes the OTHER buffer for
// the next launch. Safe across CUDA-graph replays.
__device__ unsigned int g_ep_pre, g_ep_log, g_ep_sel;
__device__ int          g_cnt2[2];
__device__ int          g_qdone[MAXB];                 // self-resetting
__device__ int          g_cidx[CAND_CAP];
__device__ float        g_cpen[CAND_CAP];
__device__ float        g_qn[MAXB * DIM];
__device__ float        g_logh[NSPLIT][(size_t)MAXB * CAND_CAP]; // 4x32MB
__device__ unsigned long long g_pk[MAXB][P_PARTS * TOPK];        // staging

// order-preserving float <-> uint (descending float == descending uint)
__device__ __forceinline__ unsigned int f2u_ord(float f) {
    unsigned int u = __float_as_uint(f);
    return (u & 0x80000000u) ? ~u : (u | 0x80000000u);
}
__device__ __forceinline__ float u2f_ord(unsigned int u) {
    return (u & 0x80000000u) ? __uint_as_float(u & 0x7FFFFFFFu)
                             : __uint_as_float(~u);
}
// 64-bit key: value (ordered) high, ~candidate-position low. Distinct keys;
// bigger == better; lower position wins ties.
__device__ __forceinline__ unsigned long long mk_key(float v, int m) {
    return ((unsigned long long)f2u_ord(v) << 32) |
           (unsigned int)(~(unsigned int)m);
}

// ---------------------------------------------------------------------------
// Kernel 1: query L2-norm + LOCAL sampled penalty bound + compaction.
// NO grid barrier: every block computes the identical bound from the same
// fixed sample (rows 0 .. 4*SVV-1), L2-cached after the first block.
//
// Soundness: groups by (vv mod 32). Group g's rows {4vv+j : vv≡g} are
// disjoint across groups, so the 32 per-group minima are attained at 32
// DISTINCT rows -> max(group minima) >= 32nd-smallest penalty. Sampling only
// loosens the bound. thresh = bound + 2*SIM_BOUND + margin never drops a
// true top-32 row of any query (|q.K|/tau <= SIM_BOUND exactly).
// ---------------------------------------------------------------------------
__global__ void __launch_bounds__(1024) k_pre(const float* __restrict__ times,
                                              const float* __restrict__ qtime,
                                              const float* __restrict__ query,
                                              int N, int B) {
    __shared__ float s[1024];
    __shared__ float sth;
    __shared__ int s_buf;
    int tid = threadIdx.x, bid = blockIdx.x;
    int nb = gridDim.x;
    int lane = tid & 31;

    // --- epoch / buffer selection: ONE ticket per block ---
    if (tid == 0) {
        unsigned int ep = atomicAdd(&g_ep_pre, 1u) / (unsigned)nb;
        int buf = (int)(ep & 1u);
        s_buf = buf;
        g_cnt2[buf ^ 1] = 0;               // pre-zero NEXT launch's buffer
    }

    // --- query L2 normalization (matches F.normalize, eps=1e-12) ---
    float v = 0.0f;
    if (bid < B && tid < DIM) v = query[bid * DIM + tid];
    {
        float ss = v * v;
        #pragma unroll
        for (int off = 16; off > 0; off >>= 1)
            ss += __shfl_xor_sync(0xFFFFFFFFu, ss, off);
        if (lane == 0) s[tid >> 5] = ss;
        __syncthreads();
        if (tid == 0) {
            float t = 0.0f;
            #pragma unroll
            for (int w = 0; w < 8; w++) t += s[w];
            s[0] = fmaxf(sqrtf(t), 1e-12f);
        }
        __syncthreads();
        float nrm = s[0];
        if (bid < B && tid < DIM) g_qn[bid * DIM + tid] = v / nrm;
        __syncthreads();                   // s reused below
    }
    int buf = s_buf;

    float qt = qtime[0];
    const float4* t4 = (const float4*)times;
    int n4 = N >> 2;

    // --- local bound from the fixed sample (every block, identical) ---
    {
        float pmin = FLT_MAX;
        #pragma unroll
        for (int r = 0; r < SVV / 1024; r++) {
            int vv = tid + r * 1024;       // vv mod 32 == tid mod 32
            if (vv < n4) {
                float4 tv = t4[vv];
                float d0 = qt - tv.x, d1 = qt - tv.y;
                float d2 = qt - tv.z, d3 = qt - tv.w;
                pmin = fminf(pmin,
                             fminf(fminf(PEN_COEF * d0 * d0, PEN_COEF * d1 * d1),
                                   fminf(PEN_COEF * d2 * d2, PEN_COEF * d3 * d3)));
            }
        }
        s[tid] = pmin;
        __syncthreads();
        #pragma unroll
        for (int st = 512; st >= 32; st >>= 1) {    // offsets % 32 == 0
            if (tid < st) s[tid] = fminf(s[tid], s[tid + st]);
            __syncthreads();
        }
        if (tid == 0) {
            float mx = -FLT_MAX;
            #pragma unroll
            for (int g = 0; g < 32; g++) mx = fmaxf(mx, s[g]);
            sth = mx + 2.0f * SIM_BOUND + 4.0f;     // sound bound + fp margin
        }
        __syncthreads();
    }
    float thresh = sth;

    // --- compaction: float4 + warp-aggregated atomic ---
    for (int vv0 = bid * 1024; vv0 < n4; vv0 += nb * 1024) {
        int vv = vv0 + tid;
        float pv[4];
        int cc[4] = {0, 0, 0, 0};
        int loc = 0;
        if (vv < n4) {
            float4 tv = t4[vv];
            float d0 = qt - tv.x, d1 = qt - tv.y, d2 = qt - tv.z, d3 = qt - tv.w;
            pv[0] = PEN_COEF * d0 * d0; pv[1] = PEN_COEF * d1 * d1;
            pv[2] = PEN_COEF * d2 * d2; pv[3] = PEN_COEF * d3 * d3;
            #pragma unroll
            for (int j = 0; j < 4; j++) { cc[j] = pv[j] <= thresh; loc += cc[j]; }
        }
        int pre = loc;                     // warp-inclusive scan; 1 atomic/warp
        #pragma unroll
        for (int off = 1; off < 32; off <<= 1) {
            int t = __shfl_up_sync(0xFFFFFFFFu, pre, off);
            if (lane >= off) pre += t;
        }
        int wtotal = __shfl_sync(0xFFFFFFFFu, pre, 31);
        if (wtotal) {
            int wbase = 0;
            if (lane == 31) wbase = atomicAdd(&g_cnt2[buf], wtotal);
            wbase = __shfl_sync(0xFFFFFFFFu, wbase, 31);
            int pos = wbase + pre - loc;
            int nbase = vv * 4;
            #pragma unroll
            for (int j = 0; j < 4; j++) {
                if (cc[j]) {
                    if (pos < CAND_CAP) { g_cidx[pos] = nbase + j; g_cpen[pos] = pv[j]; }
                    pos++;
                }
            }
        }
    }
    {   // scalar tail (N % 4)
        int rem = N - n4 * 4;
        if (bid == 0 && tid < rem) {
            int n = n4 * 4 + tid;
            float dt = qt - times[n];
            float p = PEN_COEF * dt * dt;
            if (p <= thresh) {
                int pos = atomicAdd(&g_cnt2[buf], 1);
                if (pos < CAND_CAP) { g_cidx[pos] = n; g_cpen[pos] = p; }
            }
        }
    }
}

// ---------------------------------------------------------------------------
// Kernel 2: exact fp32 partial logits, d-split 4.
// Grid (LX, ngrp), 128 threads, 48 KB dyn smem -> 4 blocks/SM. Tasks per
// group = 4*nchunks (~332) over LX=111 blocks -> imbalance ~1.003. Stores
// RAW quarter-dots; k_sel combines in fixed order (deterministic).
// ---------------------------------------------------------------------------
extern __shared__ float s_dyn[];   // qs[DIM*QG] (32 KB) then kv[DH*CG] (16 KB)

__global__ void __launch_bounds__(128, 4)
k_logits(const float* __restrict__ Kbank, int B) {
    float* qs = s_dyn;             // [d*QG + q], full depth
    float* kv = s_dyn + DIM * QG;  // [dd*CG + c], quarter depth
    __shared__ int s_cnt;

    int tid = threadIdx.x;
    int grp = blockIdx.y;

    // --- epoch / buffer selection: ONE ticket per block ---
    if (tid == 0) {
        unsigned int ep = atomicAdd(&g_ep_log, 1u) / (gridDim.x * gridDim.y);
        s_cnt = min(g_cnt2[ep & 1u], CAND_CAP);
    }
    __syncthreads();
    int cnt = s_cnt;
    if (cnt <= 0) return;
    int nch = (cnt + CG - 1) / CG;

    const float4* qn4 = (const float4*)g_qn;
    const float4* K4  = (const float4*)Kbank;

    // ---- load 32 queries transposed (full 256 d) ----
    {
        int q = tid & 31, d4b = tid >> 5;
        int b = grp * QG + q;
        #pragma unroll
        for (int i = 0; i < 16; i++) {
            int d4 = d4b + 4 * i;
            float4 v = (b < B) ? qn4[(size_t)b * (DIM / 4) + d4]
                               : make_float4(0.f, 0.f, 0.f, 0.f);
            qs[(d4 * 4 + 0) * QG + q] = v.x;
            qs[(d4 * 4 + 1) * QG + q] = v.y;
            qs[(d4 * 4 + 2) * QG + q] = v.z;
            qs[(d4 * 4 + 3) * QG + q] = v.w;
        }
    }

    int cq = tid & 15, qq = tid >> 4;
    int c0 = cq * 4, q0 = qq * 4;

    for (int t = blockIdx.x; t < NSPLIT * nch; t += gridDim.x) {
        int ch = t >> 2, h = t & 3;
        int m0 = ch * CG;
        int hb = h * DH;

        __syncthreads();   // protect kv from previous task's readers

        // ---- load 64 candidate K rows, quarter depth, transposed ----
        {
            int c = tid & 63, d4b = tid >> 6;      // d4b in 0..1
            int row = g_cidx[min(m0 + c, cnt - 1)];
            const float4* kr = K4 + (size_t)row * (DIM / 4) + hb / 4;
            #pragma unroll
            for (int i = 0; i < 8; i++) {
                int d4 = d4b + 2 * i;              // 0..15 local
                float4 v = kr[d4];
                kv[(d4 * 4 + 0) * CG + c] = v.x;
                kv[(d4 * 4 + 1) * CG + c] = v.y;
                kv[(d4 * 4 + 2) * CG + c] = v.z;
                kv[(d4 * 4 + 3) * CG + c] = v.w;
            }
        }
        __syncthreads();

        float acc[16];
        #pragma unroll
        for (int i = 0; i < 16; i++) acc[i] = 0.0f;

        #pragma unroll 4
        for (int dd = 0; dd < DH; dd++) {
            float4 kf = *(const float4*)&kv[dd * CG + c0];
            float4 qf = *(const float4*)&qs[(hb + dd) * QG + q0];
            acc[0]  += qf.x * kf.x;  acc[1]  += qf.x * kf.y;
            acc[2]  += qf.x * kf.z;  acc[3]  += qf.x * kf.w;
            acc[4]  += qf.y * kf.x;  acc[5]  += qf.y * kf.y;
            acc[6]  += qf.y * kf.z;  acc[7]  += qf.y * kf.w;
            acc[8]  += qf.z * kf.x;  acc[9]  += qf.z * kf.y;
            acc[10] += qf.z * kf.z;  acc[11] += qf.z * kf.w;
            acc[12] += qf.w * kf.x;  acc[13] += qf.w * kf.y;
            acc[14] += qf.w * kf.z;  acc[15] += qf.w * kf.w;
        }

        bool full = (m0 + c0 + 3) < cnt;
        #pragma unroll
        for (int qj = 0; qj < 4; qj++) {
            int b = grp * QG + q0 + qj;
            if (b >= B) break;
            float* dst = g_logh[h] + (size_t)b * CAND_CAP + m0 + c0;
            float4 v = make_float4(acc[qj * 4 + 0], acc[qj * 4 + 1],
                                   acc[qj * 4 + 2], acc[qj * 4 + 3]);
            if (full) {
                *(float4*)dst = v;
            } else {
                float vv[4] = {v.x, v.y, v.z, v.w};
                for (int cj = 0; cj < 4; cj++)
                    if (m0 + c0 + cj < cnt) dst[cj] = vv[cj];
            }
        }
    }
}

// ---------------------------------------------------------------------------
// Warp-0 register suffix-scan over a 256-bin histogram.
// ---------------------------------------------------------------------------
__device__ __forceinline__ void warp_cutoff(const unsigned int* h, int K,
                                            int* out, int lane) {
    unsigned int loc[8];
    int b8 = lane * 8;
    #pragma unroll
    for (int k = 0; k < 8; k++) loc[k] = h[b8 + k];
    #pragma unroll
    for (int k = 6; k >= 0; k--) loc[k] += loc[k + 1];
    unsigned int total = loc[0];
    unsigned int val = total;
    #pragma unroll
    for (int off = 1; off < 32; off <<= 1) {
        unsigned int o = __shfl_down_sync(0xFFFFFFFFu, val, off);
        if (lane + off < 32) val += o;
    }
    unsigned int excl = val - total;
    #pragma unroll
    for (int k = 0; k < 8; k++) {
        unsigned int sfx = loc[k] + excl;
        unsigned int abv = (k < 7) ? (loc[k + 1] + excl) : excl;
        if (sfx >= (unsigned)K && abv < (unsigned)K) *out = b8 + k;
    }
}

// combined logit: fixed-order 4-way add (deterministic), scale, penalty
__device__ __forceinline__ float logit_at(const float* g0, const float* g1,
                                          const float* g2, const float* g3,
                                          int m) {
    return ((g0[m] + g1[m]) + (g2[m] + g3[m])) * INV_TAU - g_cpen[m];
}

// ---------------------------------------------------------------------------
// Kernel 3: per (query, part) EXACT top-32 via radix level 0 + rank-resolve;
// LAST part block per query merges 256 staged keys by rank, softmaxes,
// gathers V, and self-resets g_qdone[b]. Grid (P_PARTS, B), 256 threads.
// ---------------------------------------------------------------------------
__global__ void __launch_bounds__(256) k_sel(const float* __restrict__ Vbank,
                                             float* __restrict__ out, int B) {
    __shared__ unsigned long long keys[EQCAP];
    __shared__ unsigned short eqi[2][EQCAP];
    __shared__ unsigned int h0[256];
    __shared__ unsigned long long wink[TOPK];
    __shared__ unsigned long long red[8];
    __shared__ int s_nwin, s_neq[2], s_b, s_last, s_buf;
    __shared__ float sv[TOPK];
    __shared__ int   si[TOPK];

    int p = blockIdx.x, b = blockIdx.y;
    int tid = threadIdx.x, lane = tid & 31, warp = tid >> 5;
    if (tid == 0) {
        unsigned int ep = atomicAdd(&g_ep_sel, 1u) / (gridDim.x * gridDim.y);
        s_buf = (int)(ep & 1u);
    }
    __syncthreads();
    int cnt = min(g_cnt2[s_buf], CAND_CAP);
    const float* g0 = g_logh[0] + (size_t)b * CAND_CAP;
    const float* g1 = g_logh[1] + (size_t)b * CAND_CAP;
    const float* g2 = g_logh[2] + (size_t)b * CAND_CAP;
    const float* g3 = g_logh[3] + (size_t)b * CAND_CAP;

    int base = (int)(((long long)cnt * p) / P_PARTS);
    int end  = (int)(((long long)cnt * (p + 1)) / P_PARTS);
    int np = end - base;
    int selk = min(TOPK, np);

    if (tid == 0) { s_nwin = 0; s_neq[0] = 0; s_neq[1] = 0; }
    h0[tid] = 0u;
    __syncthreads();

    if (np > 0 && np <= EQCAP) {
        // ---- single gmem pass: combine quarters, stage keys, histogram ----
        for (int i = tid; i < np; i += 256) {
            float v = logit_at(g0, g1, g2, g3, base + i);
            unsigned long long key = mk_key(v, base + i);
            keys[i] = key;
            unsigned int bin = (unsigned int)(key >> 56);
            unsigned int am = __activemask();
            unsigned int mk = __match_any_sync(am, bin);
            if (lane == __ffs(mk) - 1) atomicAdd(&h0[bin], __popc(mk));
        }
        __syncthreads();
        if (warp == 0) warp_cutoff(h0, selk, &s_b, lane);
        __syncthreads();
        int bs = s_b;
        for (int i = tid; i < np; i += 256) {
            int byt = (int)(keys[i] >> 56);
            if (byt > bs) {
                int q = atomicAdd(&s_nwin, 1);
                wink[q] = keys[i];
            } else if (byt == bs) {
                int q = atomicAdd(&s_neq[0], 1);
                eqi[0][q] = (unsigned short)i;
            }
        }
        __syncthreads();

        // ---- resolve equals: rank shortcut, deeper radix only if large ----
        int cur = 0;
        for (int lvl = 1; lvl < 8; lvl++) {
            int ne = s_neq[cur];
            int krem = selk - s_nwin;
            if (krem <= 0) break;
            if (ne == krem) {
                for (int i = tid; i < ne; i += 256) {
                    int q = atomicAdd(&s_nwin, 1);
                    wink[q] = keys[eqi[cur][i]];
                }
                break;
            }
            if (ne <= RANKCAP) {
                for (int i = tid; i < ne; i += 256) {
                    unsigned long long key = keys[eqi[cur][i]];
                    int rank = 0;
                    for (int j = 0; j < ne; j++)
                        rank += (keys[eqi[cur][j]] > key) ? 1 : 0;
                    if (rank < krem) {
                        int q = atomicAdd(&s_nwin, 1);
                        wink[q] = key;
                    }
                }
                break;
            }
            int sh = 56 - 8 * lvl;
            h0[tid] = 0u;
            if (tid == 0) s_neq[cur ^ 1] = 0;
            __syncthreads();
            for (int i = tid; i < ne; i += 256) {
                unsigned int bin = (unsigned int)((keys[eqi[cur][i]] >> sh) & 0xFFull);
                unsigned int am = __activemask();
                unsigned int mk = __match_any_sync(am, bin);
                if (lane == __ffs(mk) - 1) atomicAdd(&h0[bin], __popc(mk));
            }
            __syncthreads();
            if (warp == 0) warp_cutoff(h0, krem, &s_b, lane);
            __syncthreads();
            int bsl = s_b;
            for (int i = tid; i < ne; i += 256) {
                unsigned short ix = eqi[cur][i];
                int byt = (int)((keys[ix] >> sh) & 0xFFull);
                if (byt > bsl) {
                    int q = atomicAdd(&s_nwin, 1);
                    wink[q] = keys[ix];
                } else if (byt == bsl) {
                    int q = atomicAdd(&s_neq[cur ^ 1], 1);
                    eqi[cur ^ 1][q] = ix;
                }
            }
            __syncthreads();
            cur ^= 1;
        }
    } else if (np > EQCAP) {
        // ---- fallback (adversarial cnt only): non-destructive argmax ----
        unsigned long long floorkey = 0xFFFFFFFFFFFFFFFFull;
        for (int k = 0; k < selk; k++) {
            unsigned long long best = 0ull;
            for (int m = base + tid; m < end; m += 256) {
                unsigned long long key = mk_key(logit_at(g0, g1, g2, g3, m), m);
                if (key < floorkey && key > best) best = key;
            }
            #pragma unroll
            for (int off = 16; off > 0; off >>= 1) {
                unsigned long long o = __shfl_down_sync(0xFFFFFFFFu, best, off);
                if (o > best) best = o;
            }
            if (lane == 0) red[warp] = best;
            __syncthreads();
            if (tid == 0) {
                unsigned long long bb = red[0];
                #pragma unroll
                for (int w = 1; w < 8; w++) if (red[w] > bb) bb = red[w];
                wink[k] = bb;
                red[0] = bb;
            }
            __syncthreads();
            floorkey = red[0];
            __syncthreads();
        }
    }
    __syncthreads();

    // ---- write staging (pad with tiny distinct keys; real keys >= 2^32) ----
    if (tid < TOPK) {
        unsigned long long key = (tid < selk)
            ? wink[tid]
            : (unsigned long long)(p * TOPK + tid + 1);
        g_pk[b][p * TOPK + tid] = key;
    }
    __syncthreads();

    // ---- last part block for this query does the merge ----
    if (tid == 0) {
        __threadfence();
        int arrived = atomicAdd(&g_qdone[b], 1);
        s_last = (arrived == P_PARTS - 1) ? 1 : 0;
        if (s_last) g_qdone[b] = 0;        // self-reset for next launch
    }
    __syncthreads();
    if (!s_last) return;
    __threadfence();   // acquire: other parts' g_pk writes

    unsigned long long mine = g_pk[b][tid];
    keys[tid] = mine;
    __syncthreads();
    int rank = 0;
    #pragma unroll 8
    for (int j = 0; j < P_PARTS * TOPK; j++)
        rank += (keys[j] > mine) ? 1 : 0;
    if (rank < TOPK) {
        sv[rank] = u2f_ord((unsigned int)(mine >> 32));
        si[rank] = (int)(~(unsigned int)(mine & 0xFFFFFFFFull));
    }
    __syncthreads();

    // candidate position -> original row index
    if (tid < TOPK) si[tid] = g_cidx[si[tid]];
    __syncthreads();

    // softmax over the 32 selected logits (order-invariant)
    if (tid < 32) {
        float v = sv[tid];
        float mx = v;
        #pragma unroll
        for (int off = 16; off > 0; off >>= 1)
            mx = fmaxf(mx, __shfl_xor_sync(0xFFFFFFFFu, mx, off));
        float e = expf(v - mx);
        float ssum = e;
        #pragma unroll
        for (int off = 16; off > 0; off >>= 1)
            ssum += __shfl_xor_sync(0xFFFFFFFFu, ssum, off);
        sv[tid] = e / ssum;
    }
    __syncthreads();

    // gather: out[b, d] = sum_k attn[k] * V[idx_k, d]   (tid == d)
    float acc = 0.0f;
    #pragma unroll
    for (int k = 0; k < TOPK; k++)
        acc += sv[k] * Vbank[(size_t)si[k] * DIM + tid];
    out[b * DIM + tid] = acc;
}

// ---------------------------------------------------------------------------
extern "C" void kernel_launch(void* const* d_in, const int* in_sizes, int n_in,
                              void* d_out, int out_size) {
    const float* query = (const float*)d_in[0];
    const float* Kbank = (const float*)d_in[1];
    const float* Vbank = (const float*)d_in[2];
    const float* times = (const float*)d_in[3];
    const float* qtime = (const float*)d_in[4];
    float* out = (float*)d_out;

    int B = in_sizes[0] / DIM;
    int N = in_sizes[3];

    int logits_smem = (DIM * QG + DH * CG) * (int)sizeof(float);  // 48 KB
    cudaFuncSetAttribute(k_logits, cudaFuncAttributeMaxDynamicSharedMemorySize,
                         logits_smem);

    k_pre<<<PRE_BLOCKS, 1024>>>(times, qtime, query, N, B);
    dim3 g2(LX, (B + QG - 1) / QG);       // 444 blocks, 4/SM capacity
    k_logits<<<g2, 128, logits_smem>>>(Kbank, B);
    dim3 g3(P_PARTS, (unsigned)B);
    k_sel<<<g3, 256>>>(Vbank, out, B);
}

// round 13
// speedup vs baseline: 3.8667x; 3.8667x over previous
#include <cuda_runtime.h>
#include <float.h>
#include <math.h>

// Problem constants (shapes fixed by the dataset)
#define DIM       256
#define MAXB      128
#define TOPK      32
#define CAND_CAP  65536

#define INV_TAU   10.0f     // 1 / 0.1
#define PEN_COEF  0.25f     // BETA / (2*SIGMA^2) = 0.5 / 2
#define SIM_BOUND 10.0f     // max |q.K| / tau  (q, K unit-norm)

#define QG 32               // queries per logits tile
#define CG 64               // candidates per logits chunk
#define DH 128              // depth half (d-split 2)
#define NSPLIT 2
#define LX 111              // logits x-blocks (3/SM x 148 / 4 groups)
#define PRE_BLOCKS 148
#define P_PARTS 8           // selection parts per query
#define EQCAP 2048          // per-part element capacity (fast path)
#define RANKCAP 512         // rank-resolve shortcut limit
#define SVV 8192            // sampled float4s for the bound (32768 rows)

// ---------------- scratch (device globals; no allocation allowed) ----------
// Epoch-parity state: ONE ticket per BLOCK (tid==0) per kernel; epoch =
// ticket / gridSize is launch-unique and identical across all blocks of a
// launch (launches serialize on the stream). Candidate counter is double-
// buffered by epoch parity; each k_pre launch zeroes the OTHER buffer for
// the next launch. Safe across CUDA-graph replays. (Validated in R12.)
__device__ unsigned int g_ep_pre, g_ep_log, g_ep_sel;
__device__ int          g_cnt2[2];
__device__ int          g_qdone[MAXB];                 // self-resetting
__device__ int          g_cidx[CAND_CAP];
__device__ float        g_cpen[CAND_CAP];
__device__ float        g_qn[MAXB * DIM];
__device__ float        g_logh[NSPLIT][(size_t)MAXB * CAND_CAP]; // 2x32MB
__device__ unsigned long long g_pk[MAXB][P_PARTS * TOPK];        // staging

// order-preserving float <-> uint (descending float == descending uint)
__device__ __forceinline__ unsigned int f2u_ord(float f) {
    unsigned int u = __float_as_uint(f);
    return (u & 0x80000000u) ? ~u : (u | 0x80000000u);
}
__device__ __forceinline__ float u2f_ord(unsigned int u) {
    return (u & 0x80000000u) ? __uint_as_float(u & 0x7FFFFFFFu)
                             : __uint_as_float(~u);
}
// 64-bit key: value (ordered) high, ~candidate-position low. Distinct keys;
// bigger == better; lower position wins ties.
__device__ __forceinline__ unsigned long long mk_key(float v, int m) {
    return ((unsigned long long)f2u_ord(v) << 32) |
           (unsigned int)(~(unsigned int)m);
}

// ---------------------------------------------------------------------------
// Kernel 1: query L2-norm + LOCAL sampled penalty bound + compaction.
// NO grid barrier: every block computes the identical bound from the same
// fixed 32768-row sample (128 KB, L2-resident after block 0).
//
// Soundness: groups by (vv mod 32). Group g's rows {4vv+j : vv≡g} are
// disjoint across groups, so the 32 per-group minima are attained at 32
// DISTINCT rows -> max(group minima) >= 32nd-smallest penalty overall.
// Sampling only loosens the bound. thresh = bound + 2*SIM_BOUND + margin
// never drops a true top-32 row of any query (|q.K|/tau <= SIM_BOUND).
// ---------------------------------------------------------------------------
__global__ void __launch_bounds__(1024) k_pre(const float* __restrict__ times,
                                              const float* __restrict__ qtime,
                                              const float* __restrict__ query,
                                              int N, int B) {
    __shared__ float s[1024];
    __shared__ float sth;
    __shared__ int s_buf;
    int tid = threadIdx.x, bid = blockIdx.x;
    int nb = gridDim.x;
    int lane = tid & 31;

    // --- epoch / buffer selection: ONE ticket per block ---
    if (tid == 0) {
        unsigned int ep = atomicAdd(&g_ep_pre, 1u) / (unsigned)nb;
        int buf = (int)(ep & 1u);
        s_buf = buf;
        g_cnt2[buf ^ 1] = 0;               // pre-zero NEXT launch's buffer
    }

    // --- query L2 normalization (matches F.normalize, eps=1e-12) ---
    float v = 0.0f;
    if (bid < B && tid < DIM) v = query[bid * DIM + tid];
    {
        float ss = v * v;
        #pragma unroll
        for (int off = 16; off > 0; off >>= 1)
            ss += __shfl_xor_sync(0xFFFFFFFFu, ss, off);
        if (lane == 0) s[tid >> 5] = ss;
        __syncthreads();
        if (tid == 0) {
            float t = 0.0f;
            #pragma unroll
            for (int w = 0; w < 8; w++) t += s[w];
            s[0] = fmaxf(sqrtf(t), 1e-12f);
        }
        __syncthreads();
        float nrm = s[0];
        if (bid < B && tid < DIM) g_qn[bid * DIM + tid] = v / nrm;
        __syncthreads();                   // s reused below
    }
    int buf = s_buf;

    float qt = qtime[0];
    const float4* t4 = (const float4*)times;
    int n4 = N >> 2;

    // --- local bound from the fixed sample (every block, identical) ---
    {
        float pmin = FLT_MAX;
        #pragma unroll
        for (int r = 0; r < SVV / 1024; r++) {
            int vv = tid + r * 1024;       // vv mod 32 == tid mod 32
            if (vv < n4) {
                float4 tv = t4[vv];
                float d0 = qt - tv.x, d1 = qt - tv.y;
                float d2 = qt - tv.z, d3 = qt - tv.w;
                pmin = fminf(pmin,
                             fminf(fminf(PEN_COEF * d0 * d0, PEN_COEF * d1 * d1),
                                   fminf(PEN_COEF * d2 * d2, PEN_COEF * d3 * d3)));
            }
        }
        s[tid] = pmin;
        __syncthreads();
        #pragma unroll
        for (int st = 512; st >= 32; st >>= 1) {    // offsets % 32 == 0
            if (tid < st) s[tid] = fminf(s[tid], s[tid + st]);
            __syncthreads();
        }
        if (tid == 0) {
            float mx = -FLT_MAX;
            #pragma unroll
            for (int g = 0; g < 32; g++) mx = fmaxf(mx, s[g]);
            sth = mx + 2.0f * SIM_BOUND + 4.0f;     // sound bound + fp margin
        }
        __syncthreads();
    }
    float thresh = sth;

    // --- compaction: float4 + warp-aggregated atomic ---
    for (int vv0 = bid * 1024; vv0 < n4; vv0 += nb * 1024) {
        int vv = vv0 + tid;
        float pv[4];
        int cc[4] = {0, 0, 0, 0};
        int loc = 0;
        if (vv < n4) {
            float4 tv = t4[vv];
            float d0 = qt - tv.x, d1 = qt - tv.y, d2 = qt - tv.z, d3 = qt - tv.w;
            pv[0] = PEN_COEF * d0 * d0; pv[1] = PEN_COEF * d1 * d1;
            pv[2] = PEN_COEF * d2 * d2; pv[3] = PEN_COEF * d3 * d3;
            #pragma unroll
            for (int j = 0; j < 4; j++) { cc[j] = pv[j] <= thresh; loc += cc[j]; }
        }
        int pre = loc;                     // warp-inclusive scan; 1 atomic/warp
        #pragma unroll
        for (int off = 1; off < 32; off <<= 1) {
            int t = __shfl_up_sync(0xFFFFFFFFu, pre, off);
            if (lane >= off) pre += t;
        }
        int wtotal = __shfl_sync(0xFFFFFFFFu, pre, 31);
        if (wtotal) {
            int wbase = 0;
            if (lane == 31) wbase = atomicAdd(&g_cnt2[buf], wtotal);
            wbase = __shfl_sync(0xFFFFFFFFu, wbase, 31);
            int pos = wbase + pre - loc;
            int nbase = vv * 4;
            #pragma unroll
            for (int j = 0; j < 4; j++) {
                if (cc[j]) {
                    if (pos < CAND_CAP) { g_cidx[pos] = nbase + j; g_cpen[pos] = pv[j]; }
                    pos++;
                }
            }
        }
    }
    {   // scalar tail (N % 4)
        int rem = N - n4 * 4;
        if (bid == 0 && tid < rem) {
            int n = n4 * 4 + tid;
            float dt = qt - times[n];
            float p = PEN_COEF * dt * dt;
            if (p <= thresh) {
                int pos = atomicAdd(&g_cnt2[buf], 1);
                if (pos < CAND_CAP) { g_cidx[pos] = n; g_cpen[pos] = p; }
            }
        }
    }
}

// ---------------------------------------------------------------------------
// Kernel 2: exact fp32 partial logits, d-split 2 (R10-proven tiling).
// Grid (LX, ngrp), 128 threads, 64 KB dyn smem -> 3 blocks/SM. Stores RAW
// half-dots; k_sel combines (a + b) * INV_TAU - pen (order-invariant).
// ---------------------------------------------------------------------------
extern __shared__ float s_dyn[];   // qs[DIM*QG] (32 KB) then kv[DH*CG] (32 KB)

__global__ void __launch_bounds__(128, 3)
k_logits(const float* __restrict__ Kbank, int B) {
    float* qs = s_dyn;             // [d*QG + q], full depth
    float* kv = s_dyn + DIM * QG;  // [dd*CG + c], half depth
    __shared__ int s_cnt;

    int tid = threadIdx.x;
    int grp = blockIdx.y;

    // --- epoch / buffer selection: ONE ticket per block ---
    if (tid == 0) {
        unsigned int ep = atomicAdd(&g_ep_log, 1u) / (gridDim.x * gridDim.y);
        s_cnt = min(g_cnt2[ep & 1u], CAND_CAP);
    }
    __syncthreads();
    int cnt = s_cnt;
    if (cnt <= 0) return;
    int nch = (cnt + CG - 1) / CG;

    const float4* qn4 = (const float4*)g_qn;
    const float4* K4  = (const float4*)Kbank;

    // ---- load 32 queries transposed (full 256 d) ----
    {
        int q = tid & 31, d4b = tid >> 5;
        int b = grp * QG + q;
        #pragma unroll
        for (int i = 0; i < 16; i++) {
            int d4 = d4b + 4 * i;
            float4 v = (b < B) ? qn4[(size_t)b * (DIM / 4) + d4]
                               : make_float4(0.f, 0.f, 0.f, 0.f);
            qs[(d4 * 4 + 0) * QG + q] = v.x;
            qs[(d4 * 4 + 1) * QG + q] = v.y;
            qs[(d4 * 4 + 2) * QG + q] = v.z;
            qs[(d4 * 4 + 3) * QG + q] = v.w;
        }
    }

    int cq = tid & 15, qq = tid >> 4;
    int c0 = cq * 4, q0 = qq * 4;

    for (int t = blockIdx.x; t < NSPLIT * nch; t += gridDim.x) {
        int ch = t >> 1, h = t & 1;
        int m0 = ch * CG;
        int hb = h * DH;

        __syncthreads();   // protect kv from previous task's readers

        // ---- load 64 candidate K rows, half depth, transposed ----
        {
            int c = tid & 63, d4b = tid >> 6;      // d4b in 0..1
            int row = g_cidx[min(m0 + c, cnt - 1)];
            const float4* kr = K4 + (size_t)row * (DIM / 4) + hb / 4;
            #pragma unroll
            for (int i = 0; i < 16; i++) {
                int d4 = d4b + 2 * i;              // 0..31 local
                float4 v = kr[d4];
                kv[(d4 * 4 + 0) * CG + c] = v.x;
                kv[(d4 * 4 + 1) * CG + c] = v.y;
                kv[(d4 * 4 + 2) * CG + c] = v.z;
                kv[(d4 * 4 + 3) * CG + c] = v.w;
            }
        }
        __syncthreads();

        float acc[16];
        #pragma unroll
        for (int i = 0; i < 16; i++) acc[i] = 0.0f;

        #pragma unroll 4
        for (int dd = 0; dd < DH; dd++) {
            float4 kf = *(const float4*)&kv[dd * CG + c0];
            float4 qf = *(const float4*)&qs[(hb + dd) * QG + q0];
            acc[0]  += qf.x * kf.x;  acc[1]  += qf.x * kf.y;
            acc[2]  += qf.x * kf.z;  acc[3]  += qf.x * kf.w;
            acc[4]  += qf.y * kf.x;  acc[5]  += qf.y * kf.y;
            acc[6]  += qf.y * kf.z;  acc[7]  += qf.y * kf.w;
            acc[8]  += qf.z * kf.x;  acc[9]  += qf.z * kf.y;
            acc[10] += qf.z * kf.z;  acc[11] += qf.z * kf.w;
            acc[12] += qf.w * kf.x;  acc[13] += qf.w * kf.y;
            acc[14] += qf.w * kf.z;  acc[15] += qf.w * kf.w;
        }

        bool full = (m0 + c0 + 3) < cnt;
        #pragma unroll
        for (int qj = 0; qj < 4; qj++) {
            int b = grp * QG + q0 + qj;
            if (b >= B) break;
            float* dst = g_logh[h] + (size_t)b * CAND_CAP + m0 + c0;
            float4 v = make_float4(acc[qj * 4 + 0], acc[qj * 4 + 1],
                                   acc[qj * 4 + 2], acc[qj * 4 + 3]);
            if (full) {
                *(float4*)dst = v;
            } else {
                float vv[4] = {v.x, v.y, v.z, v.w};
                for (int cj = 0; cj < 4; cj++)
                    if (m0 + c0 + cj < cnt) dst[cj] = vv[cj];
            }
        }
    }
}

// ---------------------------------------------------------------------------
// Warp-0 register suffix-scan over a 256-bin histogram.
// ---------------------------------------------------------------------------
__device__ __forceinline__ void warp_cutoff(const unsigned int* h, int K,
                                            int* out, int lane) {
    unsigned int loc[8];
    int b8 = lane * 8;
    #pragma unroll
    for (int k = 0; k < 8; k++) loc[k] = h[b8 + k];
    #pragma unroll
    for (int k = 6; k >= 0; k--) loc[k] += loc[k + 1];
    unsigned int total = loc[0];
    unsigned int val = total;
    #pragma unroll
    for (int off = 1; off < 32; off <<= 1) {
        unsigned int o = __shfl_down_sync(0xFFFFFFFFu, val, off);
        if (lane + off < 32) val += o;
    }
    unsigned int excl = val - total;
    #pragma unroll
    for (int k = 0; k < 8; k++) {
        unsigned int sfx = loc[k] + excl;
        unsigned int abv = (k < 7) ? (loc[k + 1] + excl) : excl;
        if (sfx >= (unsigned)K && abv < (unsigned)K) *out = b8 + k;
    }
}

// combined logit: fixed-order 2-way add (deterministic), scale, penalty
__device__ __forceinline__ float logit_at(const float* g0, const float* g1,
                                          int m) {
    return (g0[m] + g1[m]) * INV_TAU - g_cpen[m];
}

// ---------------------------------------------------------------------------
// Kernel 3: per (query, part) EXACT top-32 via radix level 0 + rank-resolve;
// LAST part block per query merges 256 staged keys by rank, softmaxes,
// gathers V, and self-resets g_qdone[b]. Grid (P_PARTS, B), 256 threads.
// ---------------------------------------------------------------------------
__global__ void __launch_bounds__(256) k_sel(const float* __restrict__ Vbank,
                                             float* __restrict__ out, int B) {
    __shared__ unsigned long long keys[EQCAP];
    __shared__ unsigned short eqi[2][EQCAP];
    __shared__ unsigned int h0[256];
    __shared__ unsigned long long wink[TOPK];
    __shared__ unsigned long long red[8];
    __shared__ int s_nwin, s_neq[2], s_b, s_last, s_buf;
    __shared__ float sv[TOPK];
    __shared__ int   si[TOPK];

    int p = blockIdx.x, b = blockIdx.y;
    int tid = threadIdx.x, lane = tid & 31, warp = tid >> 5;
    if (tid == 0) {
        unsigned int ep = atomicAdd(&g_ep_sel, 1u) / (gridDim.x * gridDim.y);
        s_buf = (int)(ep & 1u);
    }
    __syncthreads();
    int cnt = min(g_cnt2[s_buf], CAND_CAP);
    const float* g0 = g_logh[0] + (size_t)b * CAND_CAP;
    const float* g1 = g_logh[1] + (size_t)b * CAND_CAP;

    int base = (int)(((long long)cnt * p) / P_PARTS);
    int end  = (int)(((long long)cnt * (p + 1)) / P_PARTS);
    int np = end - base;
    int selk = min(TOPK, np);

    if (tid == 0) { s_nwin = 0; s_neq[0] = 0; s_neq[1] = 0; }
    h0[tid] = 0u;
    __syncthreads();

    if (np > 0 && np <= EQCAP) {
        // ---- single gmem pass: combine halves, stage keys, histogram ----
        for (int i = tid; i < np; i += 256) {
            float v = logit_at(g0, g1, base + i);
            unsigned long long key = mk_key(v, base + i);
            keys[i] = key;
            unsigned int bin = (unsigned int)(key >> 56);
            unsigned int am = __activemask();
            unsigned int mk = __match_any_sync(am, bin);
            if (lane == __ffs(mk) - 1) atomicAdd(&h0[bin], __popc(mk));
        }
        __syncthreads();
        if (warp == 0) warp_cutoff(h0, selk, &s_b, lane);
        __syncthreads();
        int bs = s_b;
        for (int i = tid; i < np; i += 256) {
            int byt = (int)(keys[i] >> 56);
            if (byt > bs) {
                int q = atomicAdd(&s_nwin, 1);
                wink[q] = keys[i];
            } else if (byt == bs) {
                int q = atomicAdd(&s_neq[0], 1);
                eqi[0][q] = (unsigned short)i;
            }
        }
        __syncthreads();

        // ---- resolve equals: rank shortcut, deeper radix only if large ----
        int cur = 0;
        for (int lvl = 1; lvl < 8; lvl++) {
            int ne = s_neq[cur];
            int krem = selk - s_nwin;
            if (krem <= 0) break;
            if (ne == krem) {
                for (int i = tid; i < ne; i += 256) {
                    int q = atomicAdd(&s_nwin, 1);
                    wink[q] = keys[eqi[cur][i]];
                }
                break;
            }
            if (ne <= RANKCAP) {
                for (int i = tid; i < ne; i += 256) {
                    unsigned long long key = keys[eqi[cur][i]];
                    int rank = 0;
                    for (int j = 0; j < ne; j++)
                        rank += (keys[eqi[cur][j]] > key) ? 1 : 0;
                    if (rank < krem) {
                        int q = atomicAdd(&s_nwin, 1);
                        wink[q] = key;
                    }
                }
                break;
            }
            int sh = 56 - 8 * lvl;
            h0[tid] = 0u;
            if (tid == 0) s_neq[cur ^ 1] = 0;
            __syncthreads();
            for (int i = tid; i < ne; i += 256) {
                unsigned int bin = (unsigned int)((keys[eqi[cur][i]] >> sh) & 0xFFull);
                unsigned int am = __activemask();
                unsigned int mk = __match_any_sync(am, bin);
                if (lane == __ffs(mk) - 1) atomicAdd(&h0[bin], __popc(mk));
            }
            __syncthreads();
            if (warp == 0) warp_cutoff(h0, krem, &s_b, lane);
            __syncthreads();
            int bsl = s_b;
            for (int i = tid; i < ne; i += 256) {
                unsigned short ix = eqi[cur][i];
                int byt = (int)((keys[ix] >> sh) & 0xFFull);
                if (byt > bsl) {
                    int q = atomicAdd(&s_nwin, 1);
                    wink[q] = keys[ix];
                } else if (byt == bsl) {
                    int q = atomicAdd(&s_neq[cur ^ 1], 1);
                    eqi[cur ^ 1][q] = ix;
                }
            }
            __syncthreads();
            cur ^= 1;
        }
    } else if (np > EQCAP) {
        // ---- fallback (adversarial cnt only): non-destructive argmax ----
        unsigned long long floorkey = 0xFFFFFFFFFFFFFFFFull;
        for (int k = 0; k < selk; k++) {
            unsigned long long best = 0ull;
            for (int m = base + tid; m < end; m += 256) {
                unsigned long long key = mk_key(logit_at(g0, g1, m), m);
                if (key < floorkey && key > best) best = key;
            }
            #pragma unroll
            for (int off = 16; off > 0; off >>= 1) {
                unsigned long long o = __shfl_down_sync(0xFFFFFFFFu, best, off);
                if (o > best) best = o;
            }
            if (lane == 0) red[warp] = best;
            __syncthreads();
            if (tid == 0) {
                unsigned long long bb = red[0];
                #pragma unroll
                for (int w = 1; w < 8; w++) if (red[w] > bb) bb = red[w];
                wink[k] = bb;
                red[0] = bb;
            }
            __syncthreads();
            floorkey = red[0];
            __syncthreads();
        }
    }
    __syncthreads();

    // ---- write staging (pad with tiny distinct keys; real keys >= 2^32) ----
    if (tid < TOPK) {
        unsigned long long key = (tid < selk)
            ? wink[tid]
            : (unsigned long long)(p * TOPK + tid + 1);
        g_pk[b][p * TOPK + tid] = key;
    }
    __syncthreads();

    // ---- last part block for this query does the merge ----
    if (tid == 0) {
        __threadfence();
        int arrived = atomicAdd(&g_qdone[b], 1);
        s_last = (arrived == P_PARTS - 1) ? 1 : 0;
        if (s_last) g_qdone[b] = 0;        // self-reset for next launch
    }
    __syncthreads();
    if (!s_last) return;
    __threadfence();   // acquire: other parts' g_pk writes

    unsigned long long mine = g_pk[b][tid];
    keys[tid] = mine;
    __syncthreads();
    int rank = 0;
    #pragma unroll 8
    for (int j = 0; j < P_PARTS * TOPK; j++)
        rank += (keys[j] > mine) ? 1 : 0;
    if (rank < TOPK) {
        sv[rank] = u2f_ord((unsigned int)(mine >> 32));
        si[rank] = (int)(~(unsigned int)(mine & 0xFFFFFFFFull));
    }
    __syncthreads();

    // candidate position -> original row index
    if (tid < TOPK) si[tid] = g_cidx[si[tid]];
    __syncthreads();

    // softmax over the 32 selected logits (order-invariant)
    if (tid < 32) {
        float v = sv[tid];
        float mx = v;
        #pragma unroll
        for (int off = 16; off > 0; off >>= 1)
            mx = fmaxf(mx, __shfl_xor_sync(0xFFFFFFFFu, mx, off));
        float e = expf(v - mx);
        float ssum = e;
        #pragma unroll
        for (int off = 16; off > 0; off >>= 1)
            ssum += __shfl_xor_sync(0xFFFFFFFFu, ssum, off);
        sv[tid] = e / ssum;
    }
    __syncthreads();

    // gather: out[b, d] = sum_k attn[k] * V[idx_k, d]   (tid == d)
    float acc = 0.0f;
    #pragma unroll
    for (int k = 0; k < TOPK; k++)
        acc += sv[k] * Vbank[(size_t)si[k] * DIM + tid];
    out[b * DIM + tid] = acc;
}

// ---------------------------------------------------------------------------
extern "C" void kernel_launch(void* const* d_in, const int* in_sizes, int n_in,
                              void* d_out, int out_size) {
    const float* query = (const float*)d_in[0];
    const float* Kbank = (const float*)d_in[1];
    const float* Vbank = (const float*)d_in[2];
    const float* times = (const float*)d_in[3];
    const float* qtime = (const float*)d_in[4];
    float* out = (float*)d_out;

    int B = in_sizes[0] / DIM;
    int N = in_sizes[3];

    int logits_smem = (DIM * QG + DH * CG) * (int)sizeof(float);  // 64 KB
    cudaFuncSetAttribute(k_logits, cudaFuncAttributeMaxDynamicSharedMemorySize,
                         logits_smem);

    k_pre<<<PRE_BLOCKS, 1024>>>(times, qtime, query, N, B);
    dim3 g2(LX, (B + QG - 1) / QG);       // 444 blocks, 3/SM
    k_logits<<<g2, 128, logits_smem>>>(Kbank, B);
    dim3 g3(P_PARTS, (unsigned)B);
    k_sel<<<g3, 256>>>(Vbank, out, B);
}

// round 14
// speedup vs baseline: 3.8866x; 1.0052x over previous
#include <cuda_runtime.h>
#include <float.h>
#include <math.h>

// Problem constants (shapes fixed by the dataset)
#define DIM       256
#define MAXB      128
#define TOPK      32
#define CAND_CAP  65536

#define INV_TAU   10.0f     // 1 / 0.1
#define PEN_COEF  0.25f     // BETA / (2*SIGMA^2) = 0.5 / 2
#define SIM_BOUND 10.0f     // max |q.K| / tau  (q, K unit-norm)

#define QG 64               // queries per logits tile
#define CG 64               // candidates per logits chunk
#define DH 32               // depth slice (d-split 8)
#define NSPLIT 8
#define LX 222              // logits x-blocks per group (3/SM x 148 / 2)
#define PRE_BLOCKS 148
#define P_PARTS 8           // selection parts per query
#define EQCAP 2048          // per-part element capacity (fast path)
#define RANKCAP 512         // rank-resolve shortcut limit
#define SVV 8192            // sampled float4s for the bound (32768 rows)

// ---------------- scratch (device globals; no allocation allowed) ----------
// Epoch-parity state (validated R12/R13): ONE ticket per BLOCK per kernel;
// epoch = ticket / gridSize is launch-unique. Candidate counter is double-
// buffered by parity; each k_pre launch zeroes the OTHER buffer.
__device__ unsigned int g_ep_pre, g_ep_log, g_ep_sel;
__device__ int          g_cnt2[2];
__device__ int          g_qdone[MAXB];                 // self-resetting
__device__ int          g_cidx[CAND_CAP];
__device__ float        g_cpen[CAND_CAP];
__device__ float        g_qn[MAXB * DIM];
__device__ float        g_logh[NSPLIT][(size_t)MAXB * CAND_CAP]; // 8x32MB
__device__ unsigned long long g_pk[MAXB][P_PARTS * TOPK];        // staging

#define PLSTRIDE ((size_t)MAXB * CAND_CAP)

// order-preserving float <-> uint (descending float == descending uint)
__device__ __forceinline__ unsigned int f2u_ord(float f) {
    unsigned int u = __float_as_uint(f);
    return (u & 0x80000000u) ? ~u : (u | 0x80000000u);
}
__device__ __forceinline__ float u2f_ord(unsigned int u) {
    return (u & 0x80000000u) ? __uint_as_float(u & 0x7FFFFFFFu)
                             : __uint_as_float(~u);
}
// 64-bit key: value (ordered) high, ~candidate-position low. Distinct keys;
// bigger == better; lower position wins ties.
__device__ __forceinline__ unsigned long long mk_key(float v, int m) {
    return ((unsigned long long)f2u_ord(v) << 32) |
           (unsigned int)(~(unsigned int)m);
}

// ---------------------------------------------------------------------------
// Kernel 1 (unchanged from R13-proven): query L2-norm + LOCAL sampled
// penalty bound + warp-aggregated compaction. No grid barrier.
// Soundness: 32 disjoint residue groups -> max(group minima) >= 32nd-smallest
// penalty; sampling only loosens; thresh never drops a true top-32 row.
// ---------------------------------------------------------------------------
__global__ void __launch_bounds__(1024) k_pre(const float* __restrict__ times,
                                              const float* __restrict__ qtime,
                                              const float* __restrict__ query,
                                              int N, int B) {
    __shared__ float s[1024];
    __shared__ float sth;
    __shared__ int s_buf;
    int tid = threadIdx.x, bid = blockIdx.x;
    int nb = gridDim.x;
    int lane = tid & 31;

    if (tid == 0) {
        unsigned int ep = atomicAdd(&g_ep_pre, 1u) / (unsigned)nb;
        int buf = (int)(ep & 1u);
        s_buf = buf;
        g_cnt2[buf ^ 1] = 0;               // pre-zero NEXT launch's buffer
    }

    // --- query L2 normalization (matches F.normalize, eps=1e-12) ---
    float v = 0.0f;
    if (bid < B && tid < DIM) v = query[bid * DIM + tid];
    {
        float ss = v * v;
        #pragma unroll
        for (int off = 16; off > 0; off >>= 1)
            ss += __shfl_xor_sync(0xFFFFFFFFu, ss, off);
        if (lane == 0) s[tid >> 5] = ss;
        __syncthreads();
        if (tid == 0) {
            float t = 0.0f;
            #pragma unroll
            for (int w = 0; w < 8; w++) t += s[w];
            s[0] = fmaxf(sqrtf(t), 1e-12f);
        }
        __syncthreads();
        float nrm = s[0];
        if (bid < B && tid < DIM) g_qn[bid * DIM + tid] = v / nrm;
        __syncthreads();
    }
    int buf = s_buf;

    float qt = qtime[0];
    const float4* t4 = (const float4*)times;
    int n4 = N >> 2;

    // --- local bound from the fixed sample (every block, identical) ---
    {
        float pmin = FLT_MAX;
        #pragma unroll
        for (int r = 0; r < SVV / 1024; r++) {
            int vv = tid + r * 1024;       // vv mod 32 == tid mod 32
            if (vv < n4) {
                float4 tv = t4[vv];
                float d0 = qt - tv.x, d1 = qt - tv.y;
                float d2 = qt - tv.z, d3 = qt - tv.w;
                pmin = fminf(pmin,
                             fminf(fminf(PEN_COEF * d0 * d0, PEN_COEF * d1 * d1),
                                   fminf(PEN_COEF * d2 * d2, PEN_COEF * d3 * d3)));
            }
        }
        s[tid] = pmin;
        __syncthreads();
        #pragma unroll
        for (int st = 512; st >= 32; st >>= 1) {
            if (tid < st) s[tid] = fminf(s[tid], s[tid + st]);
            __syncthreads();
        }
        if (tid == 0) {
            float mx = -FLT_MAX;
            #pragma unroll
            for (int g = 0; g < 32; g++) mx = fmaxf(mx, s[g]);
            sth = mx + 2.0f * SIM_BOUND + 4.0f;
        }
        __syncthreads();
    }
    float thresh = sth;

    // --- compaction: float4 + warp-aggregated atomic ---
    for (int vv0 = bid * 1024; vv0 < n4; vv0 += nb * 1024) {
        int vv = vv0 + tid;
        float pv[4];
        int cc[4] = {0, 0, 0, 0};
        int loc = 0;
        if (vv < n4) {
            float4 tv = t4[vv];
            float d0 = qt - tv.x, d1 = qt - tv.y, d2 = qt - tv.z, d3 = qt - tv.w;
            pv[0] = PEN_COEF * d0 * d0; pv[1] = PEN_COEF * d1 * d1;
            pv[2] = PEN_COEF * d2 * d2; pv[3] = PEN_COEF * d3 * d3;
            #pragma unroll
            for (int j = 0; j < 4; j++) { cc[j] = pv[j] <= thresh; loc += cc[j]; }
        }
        int pre = loc;
        #pragma unroll
        for (int off = 1; off < 32; off <<= 1) {
            int t = __shfl_up_sync(0xFFFFFFFFu, pre, off);
            if (lane >= off) pre += t;
        }
        int wtotal = __shfl_sync(0xFFFFFFFFu, pre, 31);
        if (wtotal) {
            int wbase = 0;
            if (lane == 31) wbase = atomicAdd(&g_cnt2[buf], wtotal);
            wbase = __shfl_sync(0xFFFFFFFFu, wbase, 31);
            int pos = wbase + pre - loc;
            int nbase = vv * 4;
            #pragma unroll
            for (int j = 0; j < 4; j++) {
                if (cc[j]) {
                    if (pos < CAND_CAP) { g_cidx[pos] = nbase + j; g_cpen[pos] = pv[j]; }
                    pos++;
                }
            }
        }
    }
    {   // scalar tail (N % 4)
        int rem = N - n4 * 4;
        if (bid == 0 && tid < rem) {
            int n = n4 * 4 + tid;
            float dt = qt - times[n];
            float p = PEN_COEF * dt * dt;
            if (p <= thresh) {
                int pos = atomicAdd(&g_cnt2[buf], 1);
                if (pos < CAND_CAP) { g_cidx[pos] = n; g_cpen[pos] = p; }
            }
        }
    }
}

// ---------------------------------------------------------------------------
// Kernel 2: exact fp32 partial logits; QG=64 x CG=64 tile, d-split 8.
// 128 threads, 8q x 4c register tile (32 acc). 72 KB smem -> 3 blocks/SM.
// 2 query groups x LX=222 blocks; tasks/group = 8*nch (~640) -> makespan 3,
// imbalance ~1.04. Inner dd-step: 3x LDS.128 + 32 FMA (1.5 B/MAC, FMA-bound).
// Stores RAW slice dots; k_sel combines in a fixed deterministic tree.
// ---------------------------------------------------------------------------
extern __shared__ float s_dyn[];   // qs[DIM*QG] (64 KB) then kv[DH*CG] (8 KB)

__global__ void __launch_bounds__(128, 3)
k_logits(const float* __restrict__ Kbank, int B) {
    float* qs = s_dyn;             // [d*QG + q], full depth
    float* kv = s_dyn + DIM * QG;  // [dd*CG + c], DH slice
    __shared__ int s_cnt;

    int tid = threadIdx.x;
    int grp = blockIdx.y;

    if (tid == 0) {
        unsigned int ep = atomicAdd(&g_ep_log, 1u) / (gridDim.x * gridDim.y);
        s_cnt = min(g_cnt2[ep & 1u], CAND_CAP);
    }
    __syncthreads();
    int cnt = s_cnt;
    if (cnt <= 0) return;
    int nch = (cnt + CG - 1) / CG;

    const float4* qn4 = (const float4*)g_qn;
    const float4* K4  = (const float4*)Kbank;

    // ---- load 64 queries transposed (full 256 d) ----
    {
        int q = tid & 63, hf = tid >> 6;           // hf in 0..1
        int b = grp * QG + q;
        #pragma unroll
        for (int i = 0; i < 32; i++) {
            int d4 = hf + 2 * i;                    // 0..63
            float4 v = (b < B) ? qn4[(size_t)b * (DIM / 4) + d4]
                               : make_float4(0.f, 0.f, 0.f, 0.f);
            qs[(d4 * 4 + 0) * QG + q] = v.x;
            qs[(d4 * 4 + 1) * QG + q] = v.y;
            qs[(d4 * 4 + 2) * QG + q] = v.z;
            qs[(d4 * 4 + 3) * QG + q] = v.w;
        }
    }

    int cq = tid & 15, qq = tid >> 4;              // 16 x 8 thread grid
    int c0 = cq * 4, q0 = qq * 8;

    for (int t = blockIdx.x; t < NSPLIT * nch; t += gridDim.x) {
        int ch = t >> 3, h = t & 7;
        int m0 = ch * CG;
        int hb = h * DH;

        __syncthreads();   // protect kv from previous task's readers

        // ---- load 64 candidate K rows, DH slice, transposed ----
        {
            int c = tid & 63, d4b = tid >> 6;      // d4b in 0..1
            int row = g_cidx[min(m0 + c, cnt - 1)];
            const float4* kr = K4 + (size_t)row * (DIM / 4) + h * (DH / 4);
            #pragma unroll
            for (int i = 0; i < 4; i++) {
                int d4 = d4b + 2 * i;              // 0..7 local
                float4 v = kr[d4];
                kv[(d4 * 4 + 0) * CG + c] = v.x;
                kv[(d4 * 4 + 1) * CG + c] = v.y;
                kv[(d4 * 4 + 2) * CG + c] = v.z;
                kv[(d4 * 4 + 3) * CG + c] = v.w;
            }
        }
        __syncthreads();

        float acc[32];
        #pragma unroll
        for (int i = 0; i < 32; i++) acc[i] = 0.0f;

        #pragma unroll 4
        for (int dd = 0; dd < DH; dd++) {
            float4 kf = *(const float4*)&kv[dd * CG + c0];
            float4 qa = *(const float4*)&qs[(hb + dd) * QG + q0];
            float4 qb = *(const float4*)&qs[(hb + dd) * QG + q0 + 4];
            acc[0]  += qa.x * kf.x;  acc[1]  += qa.x * kf.y;
            acc[2]  += qa.x * kf.z;  acc[3]  += qa.x * kf.w;
            acc[4]  += qa.y * kf.x;  acc[5]  += qa.y * kf.y;
            acc[6]  += qa.y * kf.z;  acc[7]  += qa.y * kf.w;
            acc[8]  += qa.z * kf.x;  acc[9]  += qa.z * kf.y;
            acc[10] += qa.z * kf.z;  acc[11] += qa.z * kf.w;
            acc[12] += qa.w * kf.x;  acc[13] += qa.w * kf.y;
            acc[14] += qa.w * kf.z;  acc[15] += qa.w * kf.w;
            acc[16] += qb.x * kf.x;  acc[17] += qb.x * kf.y;
            acc[18] += qb.x * kf.z;  acc[19] += qb.x * kf.w;
            acc[20] += qb.y * kf.x;  acc[21] += qb.y * kf.y;
            acc[22] += qb.y * kf.z;  acc[23] += qb.y * kf.w;
            acc[24] += qb.z * kf.x;  acc[25] += qb.z * kf.y;
            acc[26] += qb.z * kf.z;  acc[27] += qb.z * kf.w;
            acc[28] += qb.w * kf.x;  acc[29] += qb.w * kf.y;
            acc[30] += qb.w * kf.z;  acc[31] += qb.w * kf.w;
        }

        bool full = (m0 + c0 + 3) < cnt;
        #pragma unroll
        for (int qj = 0; qj < 8; qj++) {
            int b = grp * QG + q0 + qj;
            if (b >= B) break;
            float* dst = g_logh[h] + (size_t)b * CAND_CAP + m0 + c0;
            float4 v = make_float4(acc[qj * 4 + 0], acc[qj * 4 + 1],
                                   acc[qj * 4 + 2], acc[qj * 4 + 3]);
            if (full) {
                *(float4*)dst = v;
            } else {
                float vv[4] = {v.x, v.y, v.z, v.w};
                for (int cj = 0; cj < 4; cj++)
                    if (m0 + c0 + cj < cnt) dst[cj] = vv[cj];
            }
        }
    }
}

// ---------------------------------------------------------------------------
// Warp-0 register suffix-scan over a 256-bin histogram.
// ---------------------------------------------------------------------------
__device__ __forceinline__ void warp_cutoff(const unsigned int* h, int K,
                                            int* out, int lane) {
    unsigned int loc[8];
    int b8 = lane * 8;
    #pragma unroll
    for (int k = 0; k < 8; k++) loc[k] = h[b8 + k];
    #pragma unroll
    for (int k = 6; k >= 0; k--) loc[k] += loc[k + 1];
    unsigned int total = loc[0];
    unsigned int val = total;
    #pragma unroll
    for (int off = 1; off < 32; off <<= 1) {
        unsigned int o = __shfl_down_sync(0xFFFFFFFFu, val, off);
        if (lane + off < 32) val += o;
    }
    unsigned int excl = val - total;
    #pragma unroll
    for (int k = 0; k < 8; k++) {
        unsigned int sfx = loc[k] + excl;
        unsigned int abv = (k < 7) ? (loc[k + 1] + excl) : excl;
        if (sfx >= (unsigned)K && abv < (unsigned)K) *out = b8 + k;
    }
}

// combined logit: fixed-order 8-way tree (deterministic), scale, penalty
__device__ __forceinline__ float logit_at(const float* gp, int m) {
    float a = (gp[m] + gp[m + PLSTRIDE]) +
              (gp[m + 2 * PLSTRIDE] + gp[m + 3 * PLSTRIDE]);
    float b = (gp[m + 4 * PLSTRIDE] + gp[m + 5 * PLSTRIDE]) +
              (gp[m + 6 * PLSTRIDE] + gp[m + 7 * PLSTRIDE]);
    return (a + b) * INV_TAU - g_cpen[m];
}

// ---------------------------------------------------------------------------
// Kernel 3: per (query, part) EXACT top-32 via radix level 0 + rank-resolve;
// LAST part block per query merges 256 staged keys by rank, softmaxes,
// gathers V, self-resets g_qdone[b]. Grid (P_PARTS, B), 256 threads.
// ---------------------------------------------------------------------------
__global__ void __launch_bounds__(256) k_sel(const float* __restrict__ Vbank,
                                             float* __restrict__ out, int B) {
    __shared__ unsigned long long keys[EQCAP];
    __shared__ unsigned short eqi[2][EQCAP];
    __shared__ unsigned int h0[256];
    __shared__ unsigned long long wink[TOPK];
    __shared__ unsigned long long red[8];
    __shared__ int s_nwin, s_neq[2], s_b, s_last, s_buf;
    __shared__ float sv[TOPK];
    __shared__ int   si[TOPK];

    int p = blockIdx.x, b = blockIdx.y;
    int tid = threadIdx.x, lane = tid & 31, warp = tid >> 5;
    if (tid == 0) {
        unsigned int ep = atomicAdd(&g_ep_sel, 1u) / (gridDim.x * gridDim.y);
        s_buf = (int)(ep & 1u);
    }
    __syncthreads();
    int cnt = min(g_cnt2[s_buf], CAND_CAP);
    const float* gp = g_logh[0] + (size_t)b * CAND_CAP;

    int base = (int)(((long long)cnt * p) / P_PARTS);
    int end  = (int)(((long long)cnt * (p + 1)) / P_PARTS);
    int np = end - base;
    int selk = min(TOPK, np);

    if (tid == 0) { s_nwin = 0; s_neq[0] = 0; s_neq[1] = 0; }
    h0[tid] = 0u;
    __syncthreads();

    if (np > 0 && np <= EQCAP) {
        // ---- single pass: combine planes, stage keys, histogram byte 7 ----
        for (int i = tid; i < np; i += 256) {
            float v = logit_at(gp, base + i);
            unsigned long long key = mk_key(v, base + i);
            keys[i] = key;
            unsigned int bin = (unsigned int)(key >> 56);
            unsigned int am = __activemask();
            unsigned int mk = __match_any_sync(am, bin);
            if (lane == __ffs(mk) - 1) atomicAdd(&h0[bin], __popc(mk));
        }
        __syncthreads();
        if (warp == 0) warp_cutoff(h0, selk, &s_b, lane);
        __syncthreads();
        int bs = s_b;
        for (int i = tid; i < np; i += 256) {
            int byt = (int)(keys[i] >> 56);
            if (byt > bs) {
                int q = atomicAdd(&s_nwin, 1);
                wink[q] = keys[i];
            } else if (byt == bs) {
                int q = atomicAdd(&s_neq[0], 1);
                eqi[0][q] = (unsigned short)i;
            }
        }
        __syncthreads();

        // ---- resolve equals: rank shortcut, deeper radix only if large ----
        int cur = 0;
        for (int lvl = 1; lvl < 8; lvl++) {
            int ne = s_neq[cur];
            int krem = selk - s_nwin;
            if (krem <= 0) break;
            if (ne == krem) {
                for (int i = tid; i < ne; i += 256) {
                    int q = atomicAdd(&s_nwin, 1);
                    wink[q] = keys[eqi[cur][i]];
                }
                break;
            }
            if (ne <= RANKCAP) {
                for (int i = tid; i < ne; i += 256) {
                    unsigned long long key = keys[eqi[cur][i]];
                    int rank = 0;
                    for (int j = 0; j < ne; j++)
                        rank += (keys[eqi[cur][j]] > key) ? 1 : 0;
                    if (rank < krem) {
                        int q = atomicAdd(&s_nwin, 1);
                        wink[q] = key;
                    }
                }
                break;
            }
            int sh = 56 - 8 * lvl;
            h0[tid] = 0u;
            if (tid == 0) s_neq[cur ^ 1] = 0;
            __syncthreads();
            for (int i = tid; i < ne; i += 256) {
                unsigned int bin = (unsigned int)((keys[eqi[cur][i]] >> sh) & 0xFFull);
                unsigned int am = __activemask();
                unsigned int mk = __match_any_sync(am, bin);
                if (lane == __ffs(mk) - 1) atomicAdd(&h0[bin], __popc(mk));
            }
            __syncthreads();
            if (warp == 0) warp_cutoff(h0, krem, &s_b, lane);
            __syncthreads();
            int bsl = s_b;
            for (int i = tid; i < ne; i += 256) {
                unsigned short ix = eqi[cur][i];
                int byt = (int)((keys[ix] >> sh) & 0xFFull);
                if (byt > bsl) {
                    int q = atomicAdd(&s_nwin, 1);
                    wink[q] = keys[ix];
                } else if (byt == bsl) {
                    int q = atomicAdd(&s_neq[cur ^ 1], 1);
                    eqi[cur ^ 1][q] = ix;
                }
            }
            __syncthreads();
            cur ^= 1;
        }
    } else if (np > EQCAP) {
        // ---- fallback (adversarial cnt only): non-destructive argmax ----
        unsigned long long floorkey = 0xFFFFFFFFFFFFFFFFull;
        for (int k = 0; k < selk; k++) {
            unsigned long long best = 0ull;
            for (int m = base + tid; m < end; m += 256) {
                unsigned long long key = mk_key(logit_at(gp, m), m);
                if (key < floorkey && key > best) best = key;
            }
            #pragma unroll
            for (int off = 16; off > 0; off >>= 1) {
                unsigned long long o = __shfl_down_sync(0xFFFFFFFFu, best, off);
                if (o > best) best = o;
            }
            if (lane == 0) red[warp] = best;
            __syncthreads();
            if (tid == 0) {
                unsigned long long bb = red[0];
                #pragma unroll
                for (int w = 1; w < 8; w++) if (red[w] > bb) bb = red[w];
                wink[k] = bb;
                red[0] = bb;
            }
            __syncthreads();
            floorkey = red[0];
            __syncthreads();
        }
    }
    __syncthreads();

    // ---- write staging (pad with tiny distinct keys; real keys >= 2^32) ----
    if (tid < TOPK) {
        unsigned long long key = (tid < selk)
            ? wink[tid]
            : (unsigned long long)(p * TOPK + tid + 1);
        g_pk[b][p * TOPK + tid] = key;
    }
    __syncthreads();

    // ---- last part block for this query does the merge ----
    if (tid == 0) {
        __threadfence();
        int arrived = atomicAdd(&g_qdone[b], 1);
        s_last = (arrived == P_PARTS - 1) ? 1 : 0;
        if (s_last) g_qdone[b] = 0;        // self-reset for next launch
    }
    __syncthreads();
    if (!s_last) return;
    __threadfence();   // acquire: other parts' g_pk writes

    unsigned long long mine = g_pk[b][tid];
    keys[tid] = mine;
    __syncthreads();
    int rank = 0;
    #pragma unroll 8
    for (int j = 0; j < P_PARTS * TOPK; j++)
        rank += (keys[j] > mine) ? 1 : 0;
    if (rank < TOPK) {
        sv[rank] = u2f_ord((unsigned int)(mine >> 32));
        si[rank] = (int)(~(unsigned int)(mine & 0xFFFFFFFFull));
    }
    __syncthreads();

    // candidate position -> original row index
    if (tid < TOPK) si[tid] = g_cidx[si[tid]];
    __syncthreads();

    // softmax over the 32 selected logits (order-invariant)
    if (tid < 32) {
        float v = sv[tid];
        float mx = v;
        #pragma unroll
        for (int off = 16; off > 0; off >>= 1)
            mx = fmaxf(mx, __shfl_xor_sync(0xFFFFFFFFu, mx, off));
        float e = expf(v - mx);
        float ssum = e;
        #pragma unroll
        for (int off = 16; off > 0; off >>= 1)
            ssum += __shfl_xor_sync(0xFFFFFFFFu, ssum, off);
        sv[tid] = e / ssum;
    }
    __syncthreads();

    // gather: out[b, d] = sum_k attn[k] * V[idx_k, d]   (tid == d)
    float acc = 0.0f;
    #pragma unroll
    for (int k = 0; k < TOPK; k++)
        acc += sv[k] * Vbank[(size_t)si[k] * DIM + tid];
    out[b * DIM + tid] = acc;
}

// ---------------------------------------------------------------------------
extern "C" void kernel_launch(void* const* d_in, const int* in_sizes, int n_in,
                              void* d_out, int out_size) {
    const float* query = (const float*)d_in[0];
    const float* Kbank = (const float*)d_in[1];
    const float* Vbank = (const float*)d_in[2];
    const float* times = (const float*)d_in[3];
    const float* qtime = (const float*)d_in[4];
    float* out = (float*)d_out;

    int B = in_sizes[0] / DIM;
    int N = in_sizes[3];

    int logits_smem = (DIM * QG + DH * CG) * (int)sizeof(float);  // 72 KB
    cudaFuncSetAttribute(k_logits, cudaFuncAttributeMaxDynamicSharedMemorySize,
                         logits_smem);

    k_pre<<<PRE_BLOCKS, 1024>>>(times, qtime, query, N, B);
    dim3 g2(LX, (B + QG - 1) / QG);       // 222 x 2 = 444 blocks = 3/SM
    k_logits<<<g2, 128, logits_smem>>>(Kbank, B);
    dim3 g3(P_PARTS, (unsigned)B);
    k_sel<<<g3, 256>>>(Vbank, out, B);
}